// round 9
// baseline (speedup 1.0000x reference)
#include <cuda_runtime.h>
#include <math.h>

#define HH 1024
#define WW 1024
#define PLANE (HH * WW)

typedef unsigned long long u64;

// Scratch: pass1 out g_sc1[s][y][x] (natural), pass2 out g_sc2[s][x][y] (transposed).
__device__ float g_sc1[(size_t)52 * PLANE];
__device__ float g_sc2[(size_t)52 * PLANE];

// ---- packed f32x2 helpers (two independent IEEE-RN lane ops per instr) ----
__device__ __forceinline__ u64 pk2(float v) {
    u64 r; asm("mov.b64 %0, {%1, %1};" : "=l"(r) : "f"(v)); return r;
}
__device__ __forceinline__ u64 fma2(u64 a, u64 b, u64 c) {   // per-lane __fmaf_rn
    u64 d; asm("fma.rn.f32x2 %0, %1, %2, %3;" : "=l"(d) : "l"(a), "l"(b), "l"(c));
    return d;
}

// ---------------------------------------------------------------------------
// Pass 1: vertical conv, FMA numerics (ascending taps, single accumulator).
// 512 threads, tile 64x x 128y; thread = x-pair (2*tx) x 8 y-outputs (f32x2).
// Direct coalesced STG.64 to g_sc1[s][y][x] (acc spans x via lanes) — no stage,
// ONE barrier per sigma. Sigma classes strided (s = c, c+NZ, ...).
// ---------------------------------------------------------------------------
__global__ __launch_bounds__(512, 2) void pass1_vert(
    const float* __restrict__ img, const float* __restrict__ k1,
    const float* __restrict__ sigmas, int S, int K, int RMAX, int NZ)
{
    extern __shared__ float sm[];
    float* skb = sm;                       // 2 * 128 kernel strips
    float* simg = sm + 256;                // ROWS * 64
    const int ROWS = 128 + 2 * RMAX + 8;

    const int tid = threadIdx.x;
    const int tx = tid & 31, ty = tid >> 5;          // ty in 0..15
    const int x0 = blockIdx.x * 64;
    const int y0 = blockIdx.y * 128;
    const int c = blockIdx.z;                        // sigma stride class

    // first strip (s = c) into buffer 0
    for (int i = tid; i < 128; i += 512) skb[i] = (i < K) ? k1[c * K + i] : 0.0f;
    // image tile with max halo (shared across this block's sigmas)
    for (int i = tid; i < ROWS * 64; i += 512) {
        int rr = i >> 6, cc = i & 63;
        int gy = y0 - RMAX + rr;
        simg[i] = ((unsigned)gy < HH) ? img[gy * WW + x0 + cc] : 0.0f;
    }
    __syncthreads();

    const u64* colp = (const u64*)simg + tx;   // 32 u64 per row

    int it = 0;
    for (int s = c; s < S; s += NZ, ++it) {
        // prefetch next strip (s+NZ) into the other buffer
        if (s + NZ < S) {
            float* nb = skb + ((it + 1) & 1) * 128;
            for (int i = tid; i < 128; i += 512)
                nb[i] = (i < K) ? k1[(s + NZ) * K + i] : 0.0f;
        }

        float sg = sigmas[s];
        int r = (int)(5.0f * sg + 0.5f) + 1;
        if (r > RMAX) r = RMAX;
        const int lenp = (2 * r + 8) & ~7;          // mult of 8; pads hit k==0
        const float* kk = skb + (it & 1) * 128 + (RMAX - r);
        const int base = ty * 8 + (RMAX - r);

        u64 w[8], acc[8];
        #pragma unroll
        for (int j = 0; j < 8; ++j) { w[j] = colp[(base + j) * 32]; acc[j] = 0ull; }
        for (int u = 0; u < lenp; u += 8) {
            #pragma unroll
            for (int uu = 0; uu < 8; ++uu) {
                u64 kv2 = pk2(kk[u + uu]);
                #pragma unroll
                for (int j = 0; j < 8; ++j)
                    acc[j] = fma2(kv2, w[(uu + j) & 7], acc[j]);
                w[uu] = colp[(base + u + uu + 8) * 32];
            }
        }
        // direct coalesced stores: lanes span x (u64 pair), fixed y per j
        float* op = g_sc1 + (size_t)s * PLANE;
        #pragma unroll
        for (int j = 0; j < 8; ++j) {
            size_t off = (size_t)(y0 + ty * 8 + j) * WW + x0 + 2 * tx;
            *(u64*)&op[off] = acc[j];
        }
        __syncthreads();   // conv reads of skb[it&1] done before it's overwritten
    }
}

// ---------------------------------------------------------------------------
// Pass 2: horizontal conv, STRICT mul-then-add numerics via two
// uncontractable packed FMAs (zero/one runtime args):
//   p   = fma.rn(k, x, zero)  == rn(k*x)   (operands >= 0, no -0 hazard)
//   acc = fma.rn(p, one, acc) == rn(acc+p)
// Tile load: coalesced rows from g_sc1[s][y][x], transposed into smem
// u64[ROWS][33] (y-pairs). Direct coalesced STG.64 to g_sc2[s][x][y].
// ---------------------------------------------------------------------------
__global__ __launch_bounds__(512, 2) void pass2_horiz(
    const float* __restrict__ k1, const float* __restrict__ sigmas,
    int S, int K, int RMAX, float zero_rt, float one_rt)
{
    extern __shared__ float sm[];
    float* sk = sm;                        // 128
    u64* stile = (u64*)(sm + 128);         // [ROWS][33] u64 (66 floats/row)
    float* sfl = sm + 128;

    const int tid = threadIdx.x;
    const int tx = tid & 31, ty = tid >> 5;
    const int y0 = blockIdx.x * 64;   // minor dim
    const int x0 = blockIdx.y * 128;  // conv dim
    const int s = blockIdx.z;

    const u64 zero2 = pk2(zero_rt);
    const u64 one2 = pk2(one_rt);

    float sg = sigmas[s];
    int r = (int)(5.0f * sg + 0.5f) + 1;
    if (r > RMAX) r = RMAX;

    for (int i = tid; i < 128; i += 512) sk[i] = (i < K) ? k1[s * K + i] : 0.0f;

    const int ROWS = 128 + 2 * r + 8;
    const float* ip = g_sc1 + (size_t)s * PLANE;   // [y][x]
    // coalesced gmem rows (vary x), transposed smem store (2-way conflict ok)
    for (int e = tid; e < 64 * ROWS; e += 512) {
        int yy = e / ROWS, xoff = e - yy * ROWS;
        int gx = x0 - r + xoff;
        float v = ((unsigned)gx < WW) ? ip[(size_t)(y0 + yy) * WW + gx] : 0.0f;
        sfl[xoff * 66 + yy] = v;
    }
    __syncthreads();

    const u64* colp = stile + tx;          // y-pair per lane
    const float* kk = sk + (RMAX - r);
    const int base = ty * 8;
    const int lenp = (2 * r + 8) & ~7;

    u64 w[8], acc[8];
    #pragma unroll
    for (int j = 0; j < 8; ++j) { w[j] = colp[(base + j) * 33]; acc[j] = zero2; }
    for (int u = 0; u < lenp; u += 8) {
        #pragma unroll
        for (int uu = 0; uu < 8; ++uu) {
            u64 kv2 = pk2(kk[u + uu]);
            #pragma unroll
            for (int j = 0; j < 8; ++j) {
                u64 p = fma2(kv2, w[(uu + j) & 7], zero2);   // rn(k*x)
                acc[j] = fma2(p, one2, acc[j]);              // rn(acc + p)
            }
            w[uu] = colp[(base + u + uu + 8) * 33];
        }
    }
    // direct coalesced stores into transposed layout [s][x][y]
    float* op = g_sc2 + (size_t)s * PLANE;
    #pragma unroll
    for (int j = 0; j < 8; ++j) {
        size_t off = (size_t)(x0 + ty * 8 + j) * HH + y0 + 2 * tx;
        *(u64*)&op[off] = acc[j];
    }
}

// ---------------------------------------------------------------------------
// Pass 3: fused DoG + 3x3x3 maxpool (pad -inf) + mask, rolling over scale s.
// Source planes are TRANSPOSED ([s][x][y]); tiles are un-transposed during
// the smem store (stride 37 => conflict-free). Everything downstream and the
// coalesced out-writes are unchanged.
// ---------------------------------------------------------------------------
__global__ __launch_bounds__(256) void pass3_dog_nms(
    const float* __restrict__ sigmas, float* __restrict__ out,
    int S, size_t out_n)
{
    __shared__ float gb[2][34 * 37];
    __shared__ float db[2][34 * 37];
    __shared__ float m2[3][1024];

    const int tid = threadIdx.x;
    const int x0 = blockIdx.x * 32 - 1;
    const int y0 = blockIdx.y * 32 - 1;
    const float NINF = -INFINITY;
    const size_t n1 = (size_t)(S - 1) * PLANE;

    for (int i = tid; i < 3 * 1024; i += 256) (&m2[0][0])[i] = NINF;

    for (int s = 0; s <= S; ++s) {
        if (s < S) {
            const float* gp = g_sc2 + (size_t)s * PLANE;   // [x][y]
            for (int i = tid; i < 34 * 34; i += 256) {
                int xx = i / 34, yy = i - xx * 34;   // inner yy: coalesced reads
                int gy = y0 + yy, gx = x0 + xx;
                gb[s & 1][yy * 37 + xx] =
                    ((unsigned)gy < HH && (unsigned)gx < WW)
                        ? gp[(size_t)gx * HH + gy] : 0.0f;
            }
        }
        __syncthreads();
        if (s >= 1 && s < S) {
            float sg = sigmas[s - 1];
            for (int i = tid; i < 34 * 34; i += 256) {
                int xx = i / 34, yy = i - xx * 34;
                int gy = y0 + yy, gx = x0 + xx;
                float v = NINF;  // -inf outside image: matches maxpool padding
                if ((unsigned)gy < HH && (unsigned)gx < WW)
                    v = __fmul_rn(__fsub_rn(gb[(s - 1) & 1][yy * 37 + xx],
                                            gb[s & 1][yy * 37 + xx]), sg);
                db[(s - 1) & 1][yy * 37 + xx] = v;
            }
        } else if (s == S) {
            for (int i = tid; i < 1024; i += 256) m2[(S - 1) % 3][i] = NINF;
        }
        __syncthreads();
        if (s >= 1 && s < S) {
            int d = s - 1;
            const float* dp0 = &db[d & 1][0];
            for (int i = tid; i < 1024; i += 256) {
                int yy = i >> 5, xx = i & 31;
                const float* dp = dp0 + yy * 37 + xx;
                float m = fmaxf(fmaxf(dp[0], dp[1]), dp[2]);
                m = fmaxf(m, fmaxf(fmaxf(dp[37], dp[38]), dp[39]));
                m = fmaxf(m, fmaxf(fmaxf(dp[74], dp[75]), dp[76]));
                m2[d % 3][i] = m;
            }
        }
        __syncthreads();
        if (s >= 2) {
            int t = s - 2;
            for (int i = tid; i < 1024; i += 256) {
                int yy = i >> 5, xx = i & 31;
                float dv = db[t & 1][(yy + 1) * 37 + (xx + 1)];
                float p = fmaxf(fmaxf(m2[(t + 2) % 3][i], m2[t % 3][i]),
                                m2[(t + 1) % 3][i]);
                int gy = y0 + 1 + yy, gx = x0 + 1 + xx;
                size_t oidx = (size_t)t * PLANE + (size_t)gy * WW + gx;
                if (oidx < out_n) out[oidx] = dv;
                size_t midx = n1 + oidx;
                if (midx < out_n)
                    out[midx] = (dv == p && dv > 0.001f) ? 1.0f : 0.0f;
            }
        }
        __syncthreads();
    }
}

__global__ void zero_tail(float* p, size_t n)
{
    size_t i = (size_t)blockIdx.x * blockDim.x + threadIdx.x;
    if (i < n) p[i] = 0.0f;
}

extern "C" void kernel_launch(void* const* d_in, const int* in_sizes, int n_in,
                              void* d_out, int out_size)
{
    const float* img = (const float*)d_in[0];
    const float* k1  = (const float*)d_in[1];
    const float* sig = (const float*)d_in[2];
    int S = in_sizes[2];               // number of sigmas
    int K = in_sizes[1] / S;           // padded 1D kernel length
    int RMAX = (K - 1) / 2;
    float* out = (float*)d_out;
    size_t n1 = (size_t)(S - 1) * PLANE;
    size_t used = 2 * n1;
    size_t on = (size_t)out_size;

    int rows = 128 + 2 * RMAX + 8;
    size_t smem1 = (size_t)(256 + rows * 64) * sizeof(float);
    size_t smem2 = (size_t)(128 + rows * 66) * sizeof(float);
    cudaFuncSetAttribute(pass1_vert, cudaFuncAttributeMaxDynamicSharedMemorySize,
                         (int)smem1);
    cudaFuncSetAttribute(pass2_horiz, cudaFuncAttributeMaxDynamicSharedMemorySize,
                         (int)smem2);

    const int NZ = 17;                 // strided sigma classes for balance
    dim3 g1(WW / 64, HH / 128, NZ);
    pass1_vert<<<g1, 512, smem1>>>(img, k1, sig, S, K, RMAX, NZ);

    // zero_rt/one_rt as runtime args: opaque to constant folding.
    volatile float z = 0.0f, o = 1.0f;
    dim3 g2(HH / 64, WW / 128, S);
    pass2_horiz<<<g2, 512, smem2>>>(k1, sig, S, K, RMAX, z, o);

    dim3 g3(WW / 32, HH / 32);
    pass3_dog_nms<<<g3, 256>>>(sig, out, S, on);

    if (on > used) {
        size_t rem = on - used;
        int blocks = (int)((rem + 255) / 256);
        zero_tail<<<blocks, 256>>>(out + used, rem);
    }
}

// round 10
// speedup vs baseline: 1.1785x; 1.1785x over previous
#include <cuda_runtime.h>
#include <math.h>

#define HH 1024
#define WW 1024
#define PLANE (HH * WW)

typedef unsigned long long u64;

// Scratch: pass1 output (transposed, [s][x][y]) and pass2 output ([s][y][x]).
__device__ float g_sc1[(size_t)52 * PLANE];
__device__ float g_sc2[(size_t)52 * PLANE];

// ---- packed f32x2 helpers (two independent IEEE-RN lane ops per instr) ----
__device__ __forceinline__ u64 pk2(float v) {
    u64 r; asm("mov.b64 %0, {%1, %1};" : "=l"(r) : "f"(v)); return r;
}
__device__ __forceinline__ u64 fma2(u64 a, u64 b, u64 c) {   // per-lane __fmaf_rn
    u64 d; asm("fma.rn.f32x2 %0, %1, %2, %3;" : "=l"(d) : "l"(a), "l"(b), "l"(c));
    return d;
}
__device__ __forceinline__ float lo2(u64 v) { return __uint_as_float((unsigned)v); }
__device__ __forceinline__ float hi2(u64 v) { return __uint_as_float((unsigned)(v >> 32)); }

// ---------------------------------------------------------------------------
// Pass 1: vertical conv, FMA numerics (ascending taps, single accumulator).
// 512 threads, tile 64x x 128y; thread = x-pair (2*tx) x 8 y-outputs (f32x2).
// Kernel strips stored DUPLICATED ({k,k} pairs) so the per-tap broadcast is
// one aligned LDS.64 (no pk2 MOV). Sigma classes strided (s = c, c+NZ, ...),
// strip double-buffer indexed by local iteration parity.
// Output transposed to g_sc1[s][x][y] via smem stage (R8 structure).
// ---------------------------------------------------------------------------
__global__ __launch_bounds__(512, 2) void pass1_vert(
    const float* __restrict__ img, const float* __restrict__ k1,
    const float* __restrict__ sigmas, int S, int K, int RMAX, int NZ)
{
    extern __shared__ float sm[];
    float* skb = sm;                       // 2 * 256 duplicated kernel strips
    float* simg = sm + 512;                // ROWS * 64
    const int ROWS = 128 + 2 * RMAX + 8;
    float* stage = simg + ROWS * 64;       // 64 * 129 (stage[x][y])

    const int tid = threadIdx.x;
    const int tx = tid & 31, ty = tid >> 5;          // ty in 0..15
    const int x0 = blockIdx.x * 64;
    const int y0 = blockIdx.y * 128;
    const int c = blockIdx.z;                        // sigma stride class

    // first strip (s = c) duplicated into buffer 0
    for (int i = tid; i < 256; i += 512)
        skb[i] = ((i >> 1) < K) ? k1[c * K + (i >> 1)] : 0.0f;
    // image tile with max halo (shared across this block's sigmas)
    for (int i = tid; i < ROWS * 64; i += 512) {
        int rr = i >> 6, cc = i & 63;
        int gy = y0 - RMAX + rr;
        simg[i] = ((unsigned)gy < HH) ? img[gy * WW + x0 + cc] : 0.0f;
    }
    __syncthreads();

    const u64* colp = (const u64*)simg + tx;   // 32 u64 per row

    int it = 0;
    for (int s = c; s < S; s += NZ, ++it) {
        // prefetch next strip (s+NZ) duplicated into the other buffer
        if (s + NZ < S) {
            float* nb = skb + ((it + 1) & 1) * 256;
            for (int i = tid; i < 256; i += 512)
                nb[i] = ((i >> 1) < K) ? k1[(s + NZ) * K + (i >> 1)] : 0.0f;
        }

        float sg = sigmas[s];
        int r = (int)(5.0f * sg + 0.5f) + 1;
        if (r > RMAX) r = RMAX;
        const int lenp = (2 * r + 8) & ~7;          // mult of 8; pads hit k==0
        const u64* kk = (const u64*)(skb + ((it & 1) * 256)) + (RMAX - r);
        const int base = ty * 8 + (RMAX - r);

        u64 w[8], acc[8];
        #pragma unroll
        for (int j = 0; j < 8; ++j) { w[j] = colp[(base + j) * 32]; acc[j] = 0ull; }
        for (int u = 0; u < lenp; u += 8) {
            #pragma unroll
            for (int uu = 0; uu < 8; ++uu) {
                u64 kv2 = kk[u + uu];                 // duplicated pair {k,k}
                #pragma unroll
                for (int j = 0; j < 8; ++j)
                    acc[j] = fma2(kv2, w[(uu + j) & 7], acc[j]);
                w[uu] = colp[(base + u + uu + 8) * 32];
            }
        }
        __syncthreads();   // prior stage reads done; strip prefetch visible next iter
        #pragma unroll
        for (int j = 0; j < 8; ++j) {
            stage[(2 * tx + 0) * 129 + ty * 8 + j] = lo2(acc[j]);
            stage[(2 * tx + 1) * 129 + ty * 8 + j] = hi2(acc[j]);
        }
        __syncthreads();
        float* op = g_sc1 + (size_t)s * PLANE + (size_t)x0 * HH + y0;
        for (int e = tid; e < 8192; e += 512) {
            int xo = e >> 7, yo = e & 127;   // consecutive e -> consecutive yo
            op[(size_t)xo * HH + yo] = stage[xo * 129 + yo];
        }
    }
}

// ---------------------------------------------------------------------------
// Pass 2: horizontal conv on transposed planes, STRICT mul-then-add numerics
// (two roundings per tap) via uncontractable packed FMAs:
//   p   = fma.rn(k, x, zero)  == rn(k*x)   (operands >= 0, no -0 hazard)
//   acc = fma.rn(p, one, acc) == rn(acc+p)
// zero/one are runtime args so no compiler can fold the FMAs into mul/add.
// Duplicated kernel strip => per-tap broadcast is one LDS.64.
// 512 threads; tile 64 minor(y) x 128 conv(x); thread = y-pair x 8 x-outputs.
// ---------------------------------------------------------------------------
__global__ __launch_bounds__(512, 2) void pass2_horiz(
    const float* __restrict__ k1, const float* __restrict__ sigmas,
    int S, int K, int RMAX, float zero_rt, float one_rt)
{
    extern __shared__ float sm[];
    float* sk = sm;                        // 256 duplicated strip
    float* stile = sm + 256;               // (128 + 2*RMAX + 8) * 64
    float* stage = stile + (128 + 2 * RMAX + 8) * 64;  // 64 * 129 (stage[y][x])

    const int tid = threadIdx.x;
    const int tx = tid & 31, ty = tid >> 5;
    const int y0 = blockIdx.x * 64;   // minor dim of transposed layout
    const int x0 = blockIdx.y * 128;  // conv dim
    const int s = blockIdx.z;

    const u64 zero2 = pk2(zero_rt);
    const u64 one2 = pk2(one_rt);

    float sg = sigmas[s];
    int r = (int)(5.0f * sg + 0.5f) + 1;
    if (r > RMAX) r = RMAX;

    for (int i = tid; i < 256; i += 512)
        sk[i] = ((i >> 1) < K) ? k1[s * K + (i >> 1)] : 0.0f;

    const int ROWS = 128 + 2 * r + 8;
    const float* ip = g_sc1 + (size_t)s * PLANE;
    for (int i = tid; i < ROWS * 64; i += 512) {
        int rr = i >> 6, cc = i & 63;
        int gx = x0 - r + rr;
        stile[i] = ((unsigned)gx < WW) ? ip[(size_t)gx * HH + y0 + cc] : 0.0f;
    }
    __syncthreads();

    const u64* colp = (const u64*)stile + tx;
    const u64* kk = (const u64*)sk + (RMAX - r);
    const int base = ty * 8;
    const int lenp = (2 * r + 8) & ~7;

    u64 w[8], acc[8];
    #pragma unroll
    for (int j = 0; j < 8; ++j) { w[j] = colp[(base + j) * 32]; acc[j] = zero2; }
    for (int u = 0; u < lenp; u += 8) {
        #pragma unroll
        for (int uu = 0; uu < 8; ++uu) {
            u64 kv2 = kk[u + uu];                     // duplicated pair {k,k}
            #pragma unroll
            for (int j = 0; j < 8; ++j) {
                u64 p = fma2(kv2, w[(uu + j) & 7], zero2);   // rn(k*x)
                acc[j] = fma2(p, one2, acc[j]);              // rn(acc + p)
            }
            w[uu] = colp[(base + u + uu + 8) * 32];
        }
    }
    #pragma unroll
    for (int j = 0; j < 8; ++j) {
        stage[(2 * tx + 0) * 129 + ty * 8 + j] = lo2(acc[j]);
        stage[(2 * tx + 1) * 129 + ty * 8 + j] = hi2(acc[j]);
    }
    __syncthreads();
    float* op = g_sc2 + (size_t)s * PLANE + (size_t)y0 * WW + x0;
    for (int e = tid; e < 8192; e += 512) {
        int yo = e >> 7, xo = e & 127;   // consecutive e -> consecutive xo
        op[(size_t)yo * WW + xo] = stage[yo * 129 + xo];
    }
}

// ---------------------------------------------------------------------------
// Pass 3: fused DoG + 3x3x3 maxpool (pad -inf) + mask, rolling over scale s.
// ---------------------------------------------------------------------------
__global__ __launch_bounds__(256) void pass3_dog_nms(
    const float* __restrict__ sigmas, float* __restrict__ out,
    int S, size_t out_n)
{
    __shared__ float gb[2][34 * 36];
    __shared__ float db[2][34 * 36];
    __shared__ float m2[3][1024];

    const int tid = threadIdx.x;
    const int x0 = blockIdx.x * 32 - 1;
    const int y0 = blockIdx.y * 32 - 1;
    const float NINF = -INFINITY;
    const size_t n1 = (size_t)(S - 1) * PLANE;

    for (int i = tid; i < 3 * 1024; i += 256) (&m2[0][0])[i] = NINF;

    for (int s = 0; s <= S; ++s) {
        if (s < S) {
            const float* gp = g_sc2 + (size_t)s * PLANE;
            for (int i = tid; i < 34 * 34; i += 256) {
                int yy = i / 34, xx = i - yy * 34;
                int gy = y0 + yy, gx = x0 + xx;
                gb[s & 1][yy * 36 + xx] =
                    ((unsigned)gy < HH && (unsigned)gx < WW) ? gp[gy * WW + gx] : 0.0f;
            }
        }
        __syncthreads();
        if (s >= 1 && s < S) {
            float sg = sigmas[s - 1];
            for (int i = tid; i < 34 * 34; i += 256) {
                int yy = i / 34, xx = i - yy * 34;
                int gy = y0 + yy, gx = x0 + xx;
                float v = NINF;  // -inf outside image: matches maxpool padding
                if ((unsigned)gy < HH && (unsigned)gx < WW)
                    v = __fmul_rn(__fsub_rn(gb[(s - 1) & 1][yy * 36 + xx],
                                            gb[s & 1][yy * 36 + xx]), sg);
                db[(s - 1) & 1][yy * 36 + xx] = v;
            }
        } else if (s == S) {
            for (int i = tid; i < 1024; i += 256) m2[(S - 1) % 3][i] = NINF;
        }
        __syncthreads();
        if (s >= 1 && s < S) {
            int d = s - 1;
            const float* dp0 = &db[d & 1][0];
            for (int i = tid; i < 1024; i += 256) {
                int yy = i >> 5, xx = i & 31;
                const float* dp = dp0 + yy * 36 + xx;
                float m = fmaxf(fmaxf(dp[0], dp[1]), dp[2]);
                m = fmaxf(m, fmaxf(fmaxf(dp[36], dp[37]), dp[38]));
                m = fmaxf(m, fmaxf(fmaxf(dp[72], dp[73]), dp[74]));
                m2[d % 3][i] = m;
            }
        }
        __syncthreads();
        if (s >= 2) {
            int t = s - 2;
            for (int i = tid; i < 1024; i += 256) {
                int yy = i >> 5, xx = i & 31;
                float dv = db[t & 1][(yy + 1) * 36 + (xx + 1)];
                float p = fmaxf(fmaxf(m2[(t + 2) % 3][i], m2[t % 3][i]),
                                m2[(t + 1) % 3][i]);
                int gy = y0 + 1 + yy, gx = x0 + 1 + xx;
                size_t oidx = (size_t)t * PLANE + (size_t)gy * WW + gx;
                if (oidx < out_n) out[oidx] = dv;
                size_t midx = n1 + oidx;
                if (midx < out_n)
                    out[midx] = (dv == p && dv > 0.001f) ? 1.0f : 0.0f;
            }
        }
        __syncthreads();
    }
}

__global__ void zero_tail(float* p, size_t n)
{
    size_t i = (size_t)blockIdx.x * blockDim.x + threadIdx.x;
    if (i < n) p[i] = 0.0f;
}

extern "C" void kernel_launch(void* const* d_in, const int* in_sizes, int n_in,
                              void* d_out, int out_size)
{
    const float* img = (const float*)d_in[0];
    const float* k1  = (const float*)d_in[1];
    const float* sig = (const float*)d_in[2];
    int S = in_sizes[2];               // number of sigmas
    int K = in_sizes[1] / S;           // padded 1D kernel length
    int RMAX = (K - 1) / 2;
    float* out = (float*)d_out;
    size_t n1 = (size_t)(S - 1) * PLANE;
    size_t used = 2 * n1;
    size_t on = (size_t)out_size;

    int rows = 128 + 2 * RMAX + 8;
    size_t smem1 = (size_t)(512 + rows * 64 + 64 * 129) * sizeof(float);
    size_t smem2 = (size_t)(256 + rows * 64 + 64 * 129) * sizeof(float);
    cudaFuncSetAttribute(pass1_vert, cudaFuncAttributeMaxDynamicSharedMemorySize,
                         (int)smem1);
    cudaFuncSetAttribute(pass2_horiz, cudaFuncAttributeMaxDynamicSharedMemorySize,
                         (int)smem2);

    const int NZ = 17;                 // strided sigma classes for balance
    dim3 g1(WW / 64, HH / 128, NZ);
    pass1_vert<<<g1, 512, smem1>>>(img, k1, sig, S, K, RMAX, NZ);

    // zero_rt/one_rt as runtime args: opaque to constant folding.
    volatile float z = 0.0f, o = 1.0f;
    dim3 g2(HH / 64, WW / 128, S);
    pass2_horiz<<<g2, 512, smem2>>>(k1, sig, S, K, RMAX, z, o);

    dim3 g3(WW / 32, HH / 32);
    pass3_dog_nms<<<g3, 256>>>(sig, out, S, on);

    if (on > used) {
        size_t rem = on - used;
        int blocks = (int)((rem + 255) / 256);
        zero_tail<<<blocks, 256>>>(out + used, rem);
    }
}

// round 11
// speedup vs baseline: 1.2356x; 1.0484x over previous
#include <cuda_runtime.h>
#include <math.h>

#define HH 1024
#define WW 1024
#define PLANE (HH * WW)

typedef unsigned long long u64;

// Scratch: pass1 output (transposed, [s][x][y]) and pass2 output ([s][y][x]).
__device__ float g_sc1[(size_t)52 * PLANE];
__device__ float g_sc2[(size_t)52 * PLANE];

// ---- packed f32x2 helpers (two independent IEEE-RN lane ops per instr) ----
__device__ __forceinline__ u64 pk2(float v) {
    u64 r; asm("mov.b64 %0, {%1, %1};" : "=l"(r) : "f"(v)); return r;
}
__device__ __forceinline__ u64 fma2(u64 a, u64 b, u64 c) {   // per-lane __fmaf_rn
    u64 d; asm("fma.rn.f32x2 %0, %1, %2, %3;" : "=l"(d) : "l"(a), "l"(b), "l"(c));
    return d;
}
__device__ __forceinline__ float lo2(u64 v) { return __uint_as_float((unsigned)v); }
__device__ __forceinline__ float hi2(u64 v) { return __uint_as_float((unsigned)(v >> 32)); }

// ---------------------------------------------------------------------------
// Pass 1: vertical conv, FMA numerics (ascending taps, single accumulator).
// 512 threads, tile 64x x 128y; thread = x-pair (2*tx) x 8 y-outputs (f32x2).
// Kernel taps prefetched 4 iterations ahead through a rolling kv[4] register
// buffer (hides the 29-cyc LDS latency). Strip buffer reads stay in-bounds
// (max index RMAX+r+11 <= 111 < 128, zeros there).
// Sigma classes strided (s = c, c+NZ, ...); strip double-buffer by it parity.
// ---------------------------------------------------------------------------
__global__ __launch_bounds__(512, 2) void pass1_vert(
    const float* __restrict__ img, const float* __restrict__ k1,
    const float* __restrict__ sigmas, int S, int K, int RMAX, int NZ)
{
    extern __shared__ float sm[];
    float* skb = sm;                       // 2 * 128 kernel strips
    float* simg = sm + 256;                // ROWS * 64
    const int ROWS = 128 + 2 * RMAX + 8;
    float* stage = simg + ROWS * 64;       // 64 * 129 (stage[x][y])

    const int tid = threadIdx.x;
    const int tx = tid & 31, ty = tid >> 5;          // ty in 0..15
    const int x0 = blockIdx.x * 64;
    const int y0 = blockIdx.y * 128;
    const int c = blockIdx.z;                        // sigma stride class

    // first strip (s = c) into buffer 0
    for (int i = tid; i < 128; i += 512) skb[i] = (i < K) ? k1[c * K + i] : 0.0f;
    // image tile with max halo (shared across this block's sigmas)
    for (int i = tid; i < ROWS * 64; i += 512) {
        int rr = i >> 6, cc = i & 63;
        int gy = y0 - RMAX + rr;
        simg[i] = ((unsigned)gy < HH) ? img[gy * WW + x0 + cc] : 0.0f;
    }
    __syncthreads();

    const u64* colp = (const u64*)simg + tx;   // 32 u64 per row

    int it = 0;
    for (int s = c; s < S; s += NZ, ++it) {
        // prefetch next strip (s+NZ) into the other buffer
        if (s + NZ < S) {
            float* nb = skb + ((it + 1) & 1) * 128;
            for (int i = tid; i < 128; i += 512)
                nb[i] = (i < K) ? k1[(s + NZ) * K + i] : 0.0f;
        }

        float sg = sigmas[s];
        int r = (int)(5.0f * sg + 0.5f) + 1;
        if (r > RMAX) r = RMAX;
        const int lenp = (2 * r + 8) & ~7;          // mult of 8; pads hit k==0
        const float* kk = skb + (it & 1) * 128 + (RMAX - r);
        const int base = ty * 8 + (RMAX - r);

        u64 w[8], acc[8];
        float kv[4];
        #pragma unroll
        for (int j = 0; j < 8; ++j) { w[j] = colp[(base + j) * 32]; acc[j] = 0ull; }
        #pragma unroll
        for (int i = 0; i < 4; ++i) kv[i] = kk[i];   // taps 0..3 preloaded
        for (int u = 0; u < lenp; u += 8) {
            #pragma unroll
            for (int uu = 0; uu < 8; ++uu) {
                u64 kv2 = pk2(kv[uu & 3]);
                kv[uu & 3] = kk[u + uu + 4];         // prefetch tap 4 ahead
                #pragma unroll
                for (int j = 0; j < 8; ++j)
                    acc[j] = fma2(kv2, w[(uu + j) & 7], acc[j]);
                w[uu] = colp[(base + u + uu + 8) * 32];
            }
        }
        __syncthreads();   // prior stage reads done; strip prefetch visible next iter
        #pragma unroll
        for (int j = 0; j < 8; ++j) {
            stage[(2 * tx + 0) * 129 + ty * 8 + j] = lo2(acc[j]);
            stage[(2 * tx + 1) * 129 + ty * 8 + j] = hi2(acc[j]);
        }
        __syncthreads();
        float* op = g_sc1 + (size_t)s * PLANE + (size_t)x0 * HH + y0;
        for (int e = tid; e < 8192; e += 512) {
            int xo = e >> 7, yo = e & 127;   // consecutive e -> consecutive yo
            op[(size_t)xo * HH + yo] = stage[xo * 129 + yo];
        }
    }
}

// ---------------------------------------------------------------------------
// Pass 2: horizontal conv on transposed planes, STRICT mul-then-add numerics
// (two roundings per tap) via uncontractable packed FMAs:
//   p   = fma.rn(k, x, zero)  == rn(k*x)   (operands >= 0, no -0 hazard)
//   acc = fma.rn(p, one, acc) == rn(acc+p)
// zero/one are runtime args so no compiler can fold the FMAs into mul/add.
// Same kv[4] rolling tap prefetch as pass1.
// 512 threads; tile 64 minor(y) x 128 conv(x); thread = y-pair x 8 x-outputs.
// ---------------------------------------------------------------------------
__global__ __launch_bounds__(512, 2) void pass2_horiz(
    const float* __restrict__ k1, const float* __restrict__ sigmas,
    int S, int K, int RMAX, float zero_rt, float one_rt)
{
    extern __shared__ float sm[];
    float* sk = sm;                        // 128
    float* stile = sm + 128;               // (128 + 2*RMAX + 8) * 64
    float* stage = stile + (128 + 2 * RMAX + 8) * 64;  // 64 * 129 (stage[y][x])

    const int tid = threadIdx.x;
    const int tx = tid & 31, ty = tid >> 5;
    const int y0 = blockIdx.x * 64;   // minor dim of transposed layout
    const int x0 = blockIdx.y * 128;  // conv dim
    const int s = blockIdx.z;

    const u64 zero2 = pk2(zero_rt);
    const u64 one2 = pk2(one_rt);

    float sg = sigmas[s];
    int r = (int)(5.0f * sg + 0.5f) + 1;
    if (r > RMAX) r = RMAX;

    for (int i = tid; i < 128; i += 512) sk[i] = (i < K) ? k1[s * K + i] : 0.0f;

    const int ROWS = 128 + 2 * r + 8;
    const float* ip = g_sc1 + (size_t)s * PLANE;
    for (int i = tid; i < ROWS * 64; i += 512) {
        int rr = i >> 6, cc = i & 63;
        int gx = x0 - r + rr;
        stile[i] = ((unsigned)gx < WW) ? ip[(size_t)gx * HH + y0 + cc] : 0.0f;
    }
    __syncthreads();

    const u64* colp = (const u64*)stile + tx;
    const float* kk = sk + (RMAX - r);
    const int base = ty * 8;
    const int lenp = (2 * r + 8) & ~7;

    u64 w[8], acc[8];
    float kv[4];
    #pragma unroll
    for (int j = 0; j < 8; ++j) { w[j] = colp[(base + j) * 32]; acc[j] = zero2; }
    #pragma unroll
    for (int i = 0; i < 4; ++i) kv[i] = kk[i];       // taps 0..3 preloaded
    for (int u = 0; u < lenp; u += 8) {
        #pragma unroll
        for (int uu = 0; uu < 8; ++uu) {
            u64 kv2 = pk2(kv[uu & 3]);
            kv[uu & 3] = kk[u + uu + 4];             // prefetch tap 4 ahead
            #pragma unroll
            for (int j = 0; j < 8; ++j) {
                u64 p = fma2(kv2, w[(uu + j) & 7], zero2);   // rn(k*x)
                acc[j] = fma2(p, one2, acc[j]);              // rn(acc + p)
            }
            w[uu] = colp[(base + u + uu + 8) * 32];
        }
    }
    #pragma unroll
    for (int j = 0; j < 8; ++j) {
        stage[(2 * tx + 0) * 129 + ty * 8 + j] = lo2(acc[j]);
        stage[(2 * tx + 1) * 129 + ty * 8 + j] = hi2(acc[j]);
    }
    __syncthreads();
    float* op = g_sc2 + (size_t)s * PLANE + (size_t)y0 * WW + x0;
    for (int e = tid; e < 8192; e += 512) {
        int yo = e >> 7, xo = e & 127;   // consecutive e -> consecutive xo
        op[(size_t)yo * WW + xo] = stage[yo * 129 + xo];
    }
}

// ---------------------------------------------------------------------------
// Pass 3: fused DoG + 3x3x3 maxpool (pad -inf) + mask, rolling over scale s.
// ---------------------------------------------------------------------------
__global__ __launch_bounds__(256) void pass3_dog_nms(
    const float* __restrict__ sigmas, float* __restrict__ out,
    int S, size_t out_n)
{
    __shared__ float gb[2][34 * 36];
    __shared__ float db[2][34 * 36];
    __shared__ float m2[3][1024];

    const int tid = threadIdx.x;
    const int x0 = blockIdx.x * 32 - 1;
    const int y0 = blockIdx.y * 32 - 1;
    const float NINF = -INFINITY;
    const size_t n1 = (size_t)(S - 1) * PLANE;

    for (int i = tid; i < 3 * 1024; i += 256) (&m2[0][0])[i] = NINF;

    for (int s = 0; s <= S; ++s) {
        if (s < S) {
            const float* gp = g_sc2 + (size_t)s * PLANE;
            for (int i = tid; i < 34 * 34; i += 256) {
                int yy = i / 34, xx = i - yy * 34;
                int gy = y0 + yy, gx = x0 + xx;
                gb[s & 1][yy * 36 + xx] =
                    ((unsigned)gy < HH && (unsigned)gx < WW) ? gp[gy * WW + gx] : 0.0f;
            }
        }
        __syncthreads();
        if (s >= 1 && s < S) {
            float sg = sigmas[s - 1];
            for (int i = tid; i < 34 * 34; i += 256) {
                int yy = i / 34, xx = i - yy * 34;
                int gy = y0 + yy, gx = x0 + xx;
                float v = NINF;  // -inf outside image: matches maxpool padding
                if ((unsigned)gy < HH && (unsigned)gx < WW)
                    v = __fmul_rn(__fsub_rn(gb[(s - 1) & 1][yy * 36 + xx],
                                            gb[s & 1][yy * 36 + xx]), sg);
                db[(s - 1) & 1][yy * 36 + xx] = v;
            }
        } else if (s == S) {
            for (int i = tid; i < 1024; i += 256) m2[(S - 1) % 3][i] = NINF;
        }
        __syncthreads();
        if (s >= 1 && s < S) {
            int d = s - 1;
            const float* dp0 = &db[d & 1][0];
            for (int i = tid; i < 1024; i += 256) {
                int yy = i >> 5, xx = i & 31;
                const float* dp = dp0 + yy * 36 + xx;
                float m = fmaxf(fmaxf(dp[0], dp[1]), dp[2]);
                m = fmaxf(m, fmaxf(fmaxf(dp[36], dp[37]), dp[38]));
                m = fmaxf(m, fmaxf(fmaxf(dp[72], dp[73]), dp[74]));
                m2[d % 3][i] = m;
            }
        }
        __syncthreads();
        if (s >= 2) {
            int t = s - 2;
            for (int i = tid; i < 1024; i += 256) {
                int yy = i >> 5, xx = i & 31;
                float dv = db[t & 1][(yy + 1) * 36 + (xx + 1)];
                float p = fmaxf(fmaxf(m2[(t + 2) % 3][i], m2[t % 3][i]),
                                m2[(t + 1) % 3][i]);
                int gy = y0 + 1 + yy, gx = x0 + 1 + xx;
                size_t oidx = (size_t)t * PLANE + (size_t)gy * WW + gx;
                if (oidx < out_n) out[oidx] = dv;
                size_t midx = n1 + oidx;
                if (midx < out_n)
                    out[midx] = (dv == p && dv > 0.001f) ? 1.0f : 0.0f;
            }
        }
        __syncthreads();
    }
}

__global__ void zero_tail(float* p, size_t n)
{
    size_t i = (size_t)blockIdx.x * blockDim.x + threadIdx.x;
    if (i < n) p[i] = 0.0f;
}

extern "C" void kernel_launch(void* const* d_in, const int* in_sizes, int n_in,
                              void* d_out, int out_size)
{
    const float* img = (const float*)d_in[0];
    const float* k1  = (const float*)d_in[1];
    const float* sig = (const float*)d_in[2];
    int S = in_sizes[2];               // number of sigmas
    int K = in_sizes[1] / S;           // padded 1D kernel length
    int RMAX = (K - 1) / 2;
    float* out = (float*)d_out;
    size_t n1 = (size_t)(S - 1) * PLANE;
    size_t used = 2 * n1;
    size_t on = (size_t)out_size;

    int rows = 128 + 2 * RMAX + 8;
    size_t smem1 = (size_t)(256 + rows * 64 + 64 * 129) * sizeof(float);
    size_t smem2 = (size_t)(128 + rows * 64 + 64 * 129) * sizeof(float);
    cudaFuncSetAttribute(pass1_vert, cudaFuncAttributeMaxDynamicSharedMemorySize,
                         (int)smem1);
    cudaFuncSetAttribute(pass2_horiz, cudaFuncAttributeMaxDynamicSharedMemorySize,
                         (int)smem2);

    const int NZ = 8;                  // strided sigma classes (R8 config)
    dim3 g1(WW / 64, HH / 128, NZ);
    pass1_vert<<<g1, 512, smem1>>>(img, k1, sig, S, K, RMAX, NZ);

    // zero_rt/one_rt as runtime args: opaque to constant folding.
    volatile float z = 0.0f, o = 1.0f;
    dim3 g2(HH / 64, WW / 128, S);
    pass2_horiz<<<g2, 512, smem2>>>(k1, sig, S, K, RMAX, z, o);

    dim3 g3(WW / 32, HH / 32);
    pass3_dog_nms<<<g3, 256>>>(sig, out, S, on);

    if (on > used) {
        size_t rem = on - used;
        int blocks = (int)((rem + 255) / 256);
        zero_tail<<<blocks, 256>>>(out + used, rem);
    }
}

// round 12
// speedup vs baseline: 1.2412x; 1.0045x over previous
#include <cuda_runtime.h>
#include <math.h>

#define HH 1024
#define WW 1024
#define PLANE (HH * WW)

typedef unsigned long long u64;

// Scratch: pass1 output (transposed, [s][x][y]) and pass2 output ([s][y][x]).
__device__ float g_sc1[(size_t)52 * PLANE];
__device__ float g_sc2[(size_t)52 * PLANE];

// ---- packed f32x2 helpers (two independent IEEE-RN lane ops per instr) ----
__device__ __forceinline__ u64 pk2(float v) {
    u64 r; asm("mov.b64 %0, {%1, %1};" : "=l"(r) : "f"(v)); return r;
}
__device__ __forceinline__ u64 fma2(u64 a, u64 b, u64 c) {   // per-lane __fmaf_rn
    u64 d; asm("fma.rn.f32x2 %0, %1, %2, %3;" : "=l"(d) : "l"(a), "l"(b), "l"(c));
    return d;
}
__device__ __forceinline__ u64 mul2(u64 a, u64 b) {          // per-lane __fmul_rn
    u64 d; asm("mul.rn.f32x2 %0, %1, %2;" : "=l"(d) : "l"(a), "l"(b)); return d;
}
__device__ __forceinline__ float lo2(u64 v) { return __uint_as_float((unsigned)v); }
__device__ __forceinline__ float hi2(u64 v) { return __uint_as_float((unsigned)(v >> 32)); }

// ---------------------------------------------------------------------------
// Pass 1: vertical conv, FMA numerics (ascending taps, single accumulator).
// 512 threads, tile 64x x 128y; thread = x-pair (2*tx) x 8 y-outputs (f32x2).
// lenp rounded to multiple of 4 (not 8): main 8-tap groups + optional 4-tap
// tail (phase 0 after the 8-aligned main loop). Pads hit zero kernel entries.
// Sigma classes strided (s = c, c+NZ, ...); strip double-buffer by it parity.
// Output transposed to g_sc1[s][x][y] via smem stage.
// ---------------------------------------------------------------------------
__global__ __launch_bounds__(512, 2) void pass1_vert(
    const float* __restrict__ img, const float* __restrict__ k1,
    const float* __restrict__ sigmas, int S, int K, int RMAX, int NZ)
{
    extern __shared__ float sm[];
    float* skb = sm;                       // 2 * 128 kernel strips
    float* simg = sm + 256;                // ROWS * 64
    const int ROWS = 128 + 2 * RMAX + 8;
    float* stage = simg + ROWS * 64;       // 64 * 129 (stage[x][y])

    const int tid = threadIdx.x;
    const int tx = tid & 31, ty = tid >> 5;          // ty in 0..15
    const int x0 = blockIdx.x * 64;
    const int y0 = blockIdx.y * 128;
    const int c = blockIdx.z;                        // sigma stride class

    // first strip (s = c) into buffer 0
    for (int i = tid; i < 128; i += 512) skb[i] = (i < K) ? k1[c * K + i] : 0.0f;
    // image tile with max halo (shared across this block's sigmas)
    for (int i = tid; i < ROWS * 64; i += 512) {
        int rr = i >> 6, cc = i & 63;
        int gy = y0 - RMAX + rr;
        simg[i] = ((unsigned)gy < HH) ? img[gy * WW + x0 + cc] : 0.0f;
    }
    __syncthreads();

    const u64* colp = (const u64*)simg + tx;   // 32 u64 per row

    int it = 0;
    for (int s = c; s < S; s += NZ, ++it) {
        // prefetch next strip (s+NZ) into the other buffer
        if (s + NZ < S) {
            float* nb = skb + ((it + 1) & 1) * 128;
            for (int i = tid; i < 128; i += 512)
                nb[i] = (i < K) ? k1[(s + NZ) * K + i] : 0.0f;
        }

        float sg = sigmas[s];
        int r = (int)(5.0f * sg + 0.5f) + 1;
        if (r > RMAX) r = RMAX;
        const int lenp = (2 * r + 4) & ~3;          // mult of 4; pads hit k==0
        const int main8 = lenp & ~7;
        const float* kk = skb + (it & 1) * 128 + (RMAX - r);
        const int base = ty * 8 + (RMAX - r);

        u64 w[8], acc[8];
        #pragma unroll
        for (int j = 0; j < 8; ++j) { w[j] = colp[(base + j) * 32]; acc[j] = 0ull; }
        for (int u = 0; u < main8; u += 8) {
            #pragma unroll
            for (int uu = 0; uu < 8; ++uu) {
                u64 kv2 = pk2(kk[u + uu]);
                #pragma unroll
                for (int j = 0; j < 8; ++j)
                    acc[j] = fma2(kv2, w[(uu + j) & 7], acc[j]);
                w[uu] = colp[(base + u + uu + 8) * 32];
            }
        }
        if (lenp & 4) {                 // 4-tap tail; phase 0 (main8 % 8 == 0)
            #pragma unroll
            for (int uu = 0; uu < 4; ++uu) {
                u64 kv2 = pk2(kk[main8 + uu]);
                #pragma unroll
                for (int j = 0; j < 8; ++j)
                    acc[j] = fma2(kv2, w[(uu + j) & 7], acc[j]);
                w[uu] = colp[(base + main8 + uu + 8) * 32];
            }
        }
        __syncthreads();   // prior stage reads done; strip prefetch visible next iter
        #pragma unroll
        for (int j = 0; j < 8; ++j) {
            stage[(2 * tx + 0) * 129 + ty * 8 + j] = lo2(acc[j]);
            stage[(2 * tx + 1) * 129 + ty * 8 + j] = hi2(acc[j]);
        }
        __syncthreads();
        float* op = g_sc1 + (size_t)s * PLANE + (size_t)x0 * HH + y0;
        for (int e = tid; e < 8192; e += 512) {
            int xo = e >> 7, yo = e & 127;   // consecutive e -> consecutive yo
            op[(size_t)xo * HH + yo] = stage[xo * 129 + yo];
        }
    }
}

// ---------------------------------------------------------------------------
// Pass 2: horizontal conv on transposed planes, STRICT mul-then-add numerics
// (two roundings per tap):
//   p   = mul.rn.f32x2(k, x)        == rn(k*x)     (true MUL, rt=2)
//   acc = fma.rn.f32x2(p, one, acc) == rn(acc + p) (x1 exact; FMA consumer =>
//                                                   no mul+add contraction)
// one is a runtime arg so ptxas cannot fold the FMA into an ADD.
// 512 threads; tile 64 minor(y) x 128 conv(x); thread = y-pair x 8 x-outputs.
// ---------------------------------------------------------------------------
__global__ __launch_bounds__(512, 2) void pass2_horiz(
    const float* __restrict__ k1, const float* __restrict__ sigmas,
    int S, int K, int RMAX, float zero_rt, float one_rt)
{
    extern __shared__ float sm[];
    float* sk = sm;                        // 128
    float* stile = sm + 128;               // (128 + 2*RMAX + 8) * 64
    float* stage = stile + (128 + 2 * RMAX + 8) * 64;  // 64 * 129 (stage[y][x])

    const int tid = threadIdx.x;
    const int tx = tid & 31, ty = tid >> 5;
    const int y0 = blockIdx.x * 64;   // minor dim of transposed layout
    const int x0 = blockIdx.y * 128;  // conv dim
    const int s = blockIdx.z;

    const u64 zero2 = pk2(zero_rt);
    const u64 one2 = pk2(one_rt);

    float sg = sigmas[s];
    int r = (int)(5.0f * sg + 0.5f) + 1;
    if (r > RMAX) r = RMAX;

    for (int i = tid; i < 128; i += 512) sk[i] = (i < K) ? k1[s * K + i] : 0.0f;

    const int ROWS = 128 + 2 * r + 8;
    const float* ip = g_sc1 + (size_t)s * PLANE;
    for (int i = tid; i < ROWS * 64; i += 512) {
        int rr = i >> 6, cc = i & 63;
        int gx = x0 - r + rr;
        stile[i] = ((unsigned)gx < WW) ? ip[(size_t)gx * HH + y0 + cc] : 0.0f;
    }
    __syncthreads();

    const u64* colp = (const u64*)stile + tx;
    const float* kk = sk + (RMAX - r);
    const int base = ty * 8;
    const int lenp = (2 * r + 4) & ~3;
    const int main8 = lenp & ~7;

    u64 w[8], acc[8];
    #pragma unroll
    for (int j = 0; j < 8; ++j) { w[j] = colp[(base + j) * 32]; acc[j] = zero2; }
    for (int u = 0; u < main8; u += 8) {
        #pragma unroll
        for (int uu = 0; uu < 8; ++uu) {
            u64 kv2 = pk2(kk[u + uu]);
            #pragma unroll
            for (int j = 0; j < 8; ++j) {
                u64 p = mul2(kv2, w[(uu + j) & 7]);          // rn(k*x)
                acc[j] = fma2(p, one2, acc[j]);              // rn(acc + p)
            }
            w[uu] = colp[(base + u + uu + 8) * 32];
        }
    }
    if (lenp & 4) {                     // 4-tap tail; phase 0
        #pragma unroll
        for (int uu = 0; uu < 4; ++uu) {
            u64 kv2 = pk2(kk[main8 + uu]);
            #pragma unroll
            for (int j = 0; j < 8; ++j) {
                u64 p = mul2(kv2, w[(uu + j) & 7]);          // rn(k*x)
                acc[j] = fma2(p, one2, acc[j]);              // rn(acc + p)
            }
            w[uu] = colp[(base + main8 + uu + 8) * 32];
        }
    }
    #pragma unroll
    for (int j = 0; j < 8; ++j) {
        stage[(2 * tx + 0) * 129 + ty * 8 + j] = lo2(acc[j]);
        stage[(2 * tx + 1) * 129 + ty * 8 + j] = hi2(acc[j]);
    }
    __syncthreads();
    float* op = g_sc2 + (size_t)s * PLANE + (size_t)y0 * WW + x0;
    for (int e = tid; e < 8192; e += 512) {
        int yo = e >> 7, xo = e & 127;   // consecutive e -> consecutive xo
        op[(size_t)yo * WW + xo] = stage[yo * 129 + xo];
    }
}

// ---------------------------------------------------------------------------
// Pass 3: fused DoG + 3x3x3 maxpool (pad -inf) + mask, rolling over scale s.
// ---------------------------------------------------------------------------
__global__ __launch_bounds__(256) void pass3_dog_nms(
    const float* __restrict__ sigmas, float* __restrict__ out,
    int S, size_t out_n)
{
    __shared__ float gb[2][34 * 36];
    __shared__ float db[2][34 * 36];
    __shared__ float m2[3][1024];

    const int tid = threadIdx.x;
    const int x0 = blockIdx.x * 32 - 1;
    const int y0 = blockIdx.y * 32 - 1;
    const float NINF = -INFINITY;
    const size_t n1 = (size_t)(S - 1) * PLANE;

    for (int i = tid; i < 3 * 1024; i += 256) (&m2[0][0])[i] = NINF;

    for (int s = 0; s <= S; ++s) {
        if (s < S) {
            const float* gp = g_sc2 + (size_t)s * PLANE;
            for (int i = tid; i < 34 * 34; i += 256) {
                int yy = i / 34, xx = i - yy * 34;
                int gy = y0 + yy, gx = x0 + xx;
                gb[s & 1][yy * 36 + xx] =
                    ((unsigned)gy < HH && (unsigned)gx < WW) ? gp[gy * WW + gx] : 0.0f;
            }
        }
        __syncthreads();
        if (s >= 1 && s < S) {
            float sg = sigmas[s - 1];
            for (int i = tid; i < 34 * 34; i += 256) {
                int yy = i / 34, xx = i - yy * 34;
                int gy = y0 + yy, gx = x0 + xx;
                float v = NINF;  // -inf outside image: matches maxpool padding
                if ((unsigned)gy < HH && (unsigned)gx < WW)
                    v = __fmul_rn(__fsub_rn(gb[(s - 1) & 1][yy * 36 + xx],
                                            gb[s & 1][yy * 36 + xx]), sg);
                db[(s - 1) & 1][yy * 36 + xx] = v;
            }
        } else if (s == S) {
            for (int i = tid; i < 1024; i += 256) m2[(S - 1) % 3][i] = NINF;
        }
        __syncthreads();
        if (s >= 1 && s < S) {
            int d = s - 1;
            const float* dp0 = &db[d & 1][0];
            for (int i = tid; i < 1024; i += 256) {
                int yy = i >> 5, xx = i & 31;
                const float* dp = dp0 + yy * 36 + xx;
                float m = fmaxf(fmaxf(dp[0], dp[1]), dp[2]);
                m = fmaxf(m, fmaxf(fmaxf(dp[36], dp[37]), dp[38]));
                m = fmaxf(m, fmaxf(fmaxf(dp[72], dp[73]), dp[74]));
                m2[d % 3][i] = m;
            }
        }
        __syncthreads();
        if (s >= 2) {
            int t = s - 2;
            for (int i = tid; i < 1024; i += 256) {
                int yy = i >> 5, xx = i & 31;
                float dv = db[t & 1][(yy + 1) * 36 + (xx + 1)];
                float p = fmaxf(fmaxf(m2[(t + 2) % 3][i], m2[t % 3][i]),
                                m2[(t + 1) % 3][i]);
                int gy = y0 + 1 + yy, gx = x0 + 1 + xx;
                size_t oidx = (size_t)t * PLANE + (size_t)gy * WW + gx;
                if (oidx < out_n) out[oidx] = dv;
                size_t midx = n1 + oidx;
                if (midx < out_n)
                    out[midx] = (dv == p && dv > 0.001f) ? 1.0f : 0.0f;
            }
        }
        __syncthreads();
    }
}

__global__ void zero_tail(float* p, size_t n)
{
    size_t i = (size_t)blockIdx.x * blockDim.x + threadIdx.x;
    if (i < n) p[i] = 0.0f;
}

extern "C" void kernel_launch(void* const* d_in, const int* in_sizes, int n_in,
                              void* d_out, int out_size)
{
    const float* img = (const float*)d_in[0];
    const float* k1  = (const float*)d_in[1];
    const float* sig = (const float*)d_in[2];
    int S = in_sizes[2];               // number of sigmas
    int K = in_sizes[1] / S;           // padded 1D kernel length
    int RMAX = (K - 1) / 2;
    float* out = (float*)d_out;
    size_t n1 = (size_t)(S - 1) * PLANE;
    size_t used = 2 * n1;
    size_t on = (size_t)out_size;

    int rows = 128 + 2 * RMAX + 8;
    size_t smem1 = (size_t)(256 + rows * 64 + 64 * 129) * sizeof(float);
    size_t smem2 = (size_t)(128 + rows * 64 + 64 * 129) * sizeof(float);
    cudaFuncSetAttribute(pass1_vert, cudaFuncAttributeMaxDynamicSharedMemorySize,
                         (int)smem1);
    cudaFuncSetAttribute(pass2_horiz, cudaFuncAttributeMaxDynamicSharedMemorySize,
                         (int)smem2);

    const int NZ = 8;                  // strided sigma classes
    dim3 g1(WW / 64, HH / 128, NZ);
    pass1_vert<<<g1, 512, smem1>>>(img, k1, sig, S, K, RMAX, NZ);

    // zero_rt/one_rt as runtime args: opaque to constant folding.
    volatile float z = 0.0f, o = 1.0f;
    dim3 g2(HH / 64, WW / 128, S);
    pass2_horiz<<<g2, 512, smem2>>>(k1, sig, S, K, RMAX, z, o);

    dim3 g3(WW / 32, HH / 32);
    pass3_dog_nms<<<g3, 256>>>(sig, out, S, on);

    if (on > used) {
        size_t rem = on - used;
        int blocks = (int)((rem + 255) / 256);
        zero_tail<<<blocks, 256>>>(out + used, rem);
    }
}